// round 8
// baseline (speedup 1.0000x reference)
#include <cuda_runtime.h>
#include <cuda_bf16.h>
#include <math.h>

// ---------------------------------------------------------------------------
// Static scratch (no allocation allowed): bf16 hi/lo split masked weights.
// Layout [K][N] row-major (same as source fp32 weights).
// ---------------------------------------------------------------------------
__device__ __nv_bfloat16 g_Wc_hi[1024 * 1024];
__device__ __nv_bfloat16 g_Wc_lo[1024 * 1024];
__device__ __nv_bfloat16 g_Wp_hi[1024 * 1024];
__device__ __nv_bfloat16 g_Wp_lo[1024 * 1024];

// ---------------------------------------------------------------------------
// MMA / ldmatrix primitives.
// ---------------------------------------------------------------------------
__device__ __forceinline__ void ldsm4(unsigned r[4], unsigned addr) {
    asm volatile("ldmatrix.sync.aligned.m8n8.x4.shared.b16 {%0,%1,%2,%3}, [%4];"
                 : "=r"(r[0]), "=r"(r[1]), "=r"(r[2]), "=r"(r[3]) : "r"(addr));
}
__device__ __forceinline__ void ldsm4t(unsigned r[4], unsigned addr) {
    asm volatile("ldmatrix.sync.aligned.m8n8.x4.trans.shared.b16 {%0,%1,%2,%3}, [%4];"
                 : "=r"(r[0]), "=r"(r[1]), "=r"(r[2]), "=r"(r[3]) : "r"(addr));
}
__device__ __forceinline__ void mma16816(float d[4], const unsigned a[4],
                                         const unsigned b[2]) {
    asm volatile(
        "mma.sync.aligned.m16n8k16.row.col.f32.bf16.bf16.f32 "
        "{%0,%1,%2,%3}, {%4,%5,%6,%7}, {%8,%9}, {%0,%1,%2,%3};"
        : "+f"(d[0]), "+f"(d[1]), "+f"(d[2]), "+f"(d[3])
        : "r"(a[0]), "r"(a[1]), "r"(a[2]), "r"(a[3]), "r"(b[0]), "r"(b[1]));
}
__device__ __forceinline__ unsigned pack_bf(__nv_bfloat16 a, __nv_bfloat16 b) {
    unsigned short ua = *(unsigned short*)&a;
    unsigned short ub = *(unsigned short*)&b;
    return (unsigned)ua | ((unsigned)ub << 16);
}
__device__ __forceinline__ void split2(float v0, float v1,
                                       unsigned& hi, unsigned& lo) {
    __nv_bfloat16 h0 = __float2bfloat16_rn(v0);
    __nv_bfloat16 h1 = __float2bfloat16_rn(v1);
    __nv_bfloat16 l0 = __float2bfloat16_rn(v0 - __bfloat162float(h0));
    __nv_bfloat16 l1 = __float2bfloat16_rn(v1 - __bfloat162float(h1));
    hi = pack_bf(h0, h1);
    lo = pack_bf(l0, l1);
}

// ---------------------------------------------------------------------------
// Build masked weights, split into bf16 hi/lo. One block per unit (column u).
// ---------------------------------------------------------------------------
__global__ void build_mask_kernel(const float* __restrict__ W,
                                  const float* __restrict__ mu,
                                  const float* __restrict__ sigma,
                                  __nv_bfloat16* __restrict__ Whi,
                                  __nv_bfloat16* __restrict__ Wlo,
                                  int n_in, int units, float scale) {
    int u = blockIdx.x;
    float m = mu[u];
    float s = sigma[u];
    s = fminf(fmaxf(s, 0.01f), 1.0f);
    float inv2s2 = 1.0f / (2.0f * s * s);
    float inv_nm1 = 1.0f / (float)(n_in - 1);

    float ss = 0.0f;
    for (int d = threadIdx.x; d < n_in; d += blockDim.x) {
        float diff = (float)d * inv_nm1 - m;
        float e = expf(-diff * diff * inv2s2);
        ss += e * e;
    }
    __shared__ float red[32];
    #pragma unroll
    for (int o = 16; o > 0; o >>= 1) ss += __shfl_down_sync(0xffffffffu, ss, o);
    if ((threadIdx.x & 31) == 0) red[threadIdx.x >> 5] = ss;
    __syncthreads();
    if (threadIdx.x < 32) {
        int nwarp = (blockDim.x + 31) >> 5;
        float v = (threadIdx.x < nwarp) ? red[threadIdx.x] : 0.0f;
        #pragma unroll
        for (int o = 16; o > 0; o >>= 1) v += __shfl_down_sync(0xffffffffu, v, o);
        if (threadIdx.x == 0) red[0] = v;
    }
    __syncthreads();
    float factor = scale * rsqrtf(red[0]);

    for (int d = threadIdx.x; d < n_in; d += blockDim.x) {
        float diff = (float)d * inv_nm1 - m;
        float e = expf(-diff * diff * inv2s2);
        float w = W[(size_t)d * units + u] * (e * factor);
        __nv_bfloat16 h = __float2bfloat16_rn(w);
        __nv_bfloat16 l = __float2bfloat16_rn(w - __bfloat162float(h));
        Whi[(size_t)d * units + u] = h;
        Wlo[(size_t)d * units + u] = l;
    }
}

// ---------------------------------------------------------------------------
// Big GEMM (M16=2 path of R6, unchanged): BM=64, BN=64, BK=32, 256 threads.
// ---------------------------------------------------------------------------
__global__ void __launch_bounds__(256) mma_gemm_big(
    const float* A, size_t lda,
    const __nv_bfloat16* __restrict__ Bhi_g,
    const __nv_bfloat16* __restrict__ Blo_g,
    const float* __restrict__ bias,
    float* C, size_t ldc, int N, int K)
{
    constexpr int BM = 64;
    constexpr int APITCH = 112;
    constexpr int BPITCH = 144;
    constexpr int A_PL = BM * APITCH;
    constexpr int B_PL = 32 * BPITCH;
    constexpr int STAGE = 2 * A_PL + 2 * B_PL;

    extern __shared__ char smem[];
    const unsigned sbase = (unsigned)__cvta_generic_to_shared(smem);

    const int tid  = threadIdx.x;
    const int lane = tid & 31;
    const int wid  = tid >> 5;
    const int wm   = wid & 1;
    const int wn   = wid >> 1;
    const int m0   = blockIdx.y * BM;
    const int n0   = blockIdx.x * 64;

    float4 ra0, ra1;
    uint4  rbh, rbl;

    const unsigned aBase = sbase + (unsigned)((wm * 32 + (lane & 15)) * APITCH
                                              + (lane >> 4) * 16);
    const unsigned bBase = sbase + (unsigned)(2 * A_PL + (lane & 15) * BPITCH
                                              + (lane >> 4) * 16 + wn * 32);

    float accH[2][2][4], accX[2][2][4];
    #pragma unroll
    for (int i = 0; i < 2; i++)
        #pragma unroll
        for (int j = 0; j < 2; j++)
            #pragma unroll
            for (int q = 0; q < 4; q++) { accH[i][j][q] = 0.f; accX[i][j][q] = 0.f; }

    auto ldgA = [&](int k0) {
        const float* p = A + (size_t)(m0 + (tid >> 2)) * lda + k0 + (tid & 3) * 8;
        ra0 = *(const float4*)p;
        ra1 = *(const float4*)(p + 4);
    };
    auto ldgB = [&](int k0) {
        size_t off = (size_t)(k0 + (tid >> 3)) * N + n0 + (tid & 7) * 8;
        rbh = *(const uint4*)(Bhi_g + off);
        rbl = *(const uint4*)(Blo_g + off);
    };
    auto stsAB = [&](int st) {
        char* base = smem + st * STAGE;
        const int row = tid >> 2, kc = (tid & 3) * 8;
        unsigned h0, l0, h1, l1, h2, l2, h3, l3;
        split2(ra0.x, ra0.y, h0, l0);
        split2(ra0.z, ra0.w, h1, l1);
        split2(ra1.x, ra1.y, h2, l2);
        split2(ra1.z, ra1.w, h3, l3);
        *(uint2*)(base + row * APITCH + kc * 2)            = make_uint2(h0, h1);
        *(uint2*)(base + row * APITCH + kc * 2 + 8)        = make_uint2(h2, h3);
        *(uint2*)(base + A_PL + row * APITCH + kc * 2)     = make_uint2(l0, l1);
        *(uint2*)(base + A_PL + row * APITCH + kc * 2 + 8) = make_uint2(l2, l3);
        const int krow = tid >> 3, nc = (tid & 7) * 8;
        *(uint4*)(base + 2 * A_PL + krow * BPITCH + nc * 2)        = rbh;
        *(uint4*)(base + 2 * A_PL + B_PL + krow * BPITCH + nc * 2) = rbl;
    };
    auto compute = [&](int st) {
        const unsigned sOff = (unsigned)(st * STAGE);
        #pragma unroll
        for (int c = 0; c < 2; c++) {
            unsigned ah[2][4], al[2][4], bh[4], bl[4];
            #pragma unroll
            for (int i = 0; i < 2; i++) {
                ldsm4(ah[i], aBase + sOff + i * (16 * APITCH) + c * 32);
                ldsm4(al[i], aBase + sOff + A_PL + i * (16 * APITCH) + c * 32);
            }
            ldsm4t(bh, bBase + sOff + c * (16 * BPITCH));
            ldsm4t(bl, bBase + sOff + B_PL + c * (16 * BPITCH));
            #pragma unroll
            for (int i = 0; i < 2; i++)
                #pragma unroll
                for (int j = 0; j < 2; j++) {
                    mma16816(accH[i][j], ah[i], bh + 2 * j);
                    mma16816(accX[i][j], ah[i], bl + 2 * j);
                    mma16816(accX[i][j], al[i], bh + 2 * j);
                }
        }
    };

    const int NIT = K / 32;
    ldgA(0); ldgB(0);
    stsAB(0);
    __syncthreads();
    int s = 0;
    for (int it = 0; it < NIT; it++) {
        if (it + 1 < NIT) { ldgA((it + 1) * 32); ldgB((it + 1) * 32); }
        compute(s);
        if (it + 1 < NIT) {
            stsAB(s ^ 1);
            __syncthreads();
            s ^= 1;
        }
    }

    #pragma unroll
    for (int i = 0; i < 2; i++) {
        const int mBase = m0 + wm * 32 + i * 16 + (lane >> 2);
        #pragma unroll
        for (int j = 0; j < 2; j++) {
            const int nBase = n0 + wn * 16 + j * 8 + 2 * (lane & 3);
            #pragma unroll
            for (int h = 0; h < 2; h++) {
                const int m = mBase + h * 8;
                float d0 = accH[i][j][2 * h + 0] + accX[i][j][2 * h + 0];
                float d1 = accH[i][j][2 * h + 1] + accX[i][j][2 * h + 1];
                float2 o;
                o.x = d0 + bias[nBase];
                o.y = d1 + bias[nBase + 1];
                *(float2*)(C + (size_t)m * ldc + nBase) = o;
            }
        }
    }
}

// ---------------------------------------------------------------------------
// Step GEMM v2: C = tanh(C + A @ B) in place.
// BM=32, BN=32, BK=32, 128 threads (4 warps: 2m x 2n, warp tile 16x16).
// Grid (U/32, B/32) = 256 CTAs -> 2 CTAs/SM: two independent barrier domains
// per SM so one CTA computes while the other waits on LDG/barrier.
// SMEM/stage: A hi/lo 2*32*112 + B hi/lo 2*32*80 = 12288 B; 2 stages = 24 KB.
// ---------------------------------------------------------------------------
__global__ void __launch_bounds__(128) mma_gemm_step(
    const float* A, size_t lda,
    const __nv_bfloat16* __restrict__ Bhi_g,
    const __nv_bfloat16* __restrict__ Blo_g,
    float* C, size_t ldc, int N, int K)
{
    constexpr int APITCH = 112;
    constexpr int BPITCH = 80;
    constexpr int A_PL = 32 * APITCH;
    constexpr int B_PL = 32 * BPITCH;
    constexpr int STAGE = 2 * A_PL + 2 * B_PL;

    extern __shared__ char smem[];
    const unsigned sbase = (unsigned)__cvta_generic_to_shared(smem);

    const int tid  = threadIdx.x;
    const int lane = tid & 31;
    const int wid  = tid >> 5;
    const int wm   = wid & 1;                  // 0..1
    const int wn   = wid >> 1;                 // 0..1
    const int m0   = blockIdx.y * 32;
    const int n0   = blockIdx.x * 32;

    float4 ra0, ra1;
    uint4  rbh, rbl;

    const unsigned aBase = sbase + (unsigned)((wm * 16 + (lane & 15)) * APITCH
                                              + (lane >> 4) * 16);
    const unsigned bBase = sbase + (unsigned)(2 * A_PL + (lane & 15) * BPITCH
                                              + (lane >> 4) * 16 + wn * 32);

    float accH[2][4], accX[2][4];
    #pragma unroll
    for (int j = 0; j < 2; j++)
        #pragma unroll
        for (int q = 0; q < 4; q++) { accH[j][q] = 0.f; accX[j][q] = 0.f; }

    auto ldgA = [&](int k0) {
        const float* p = A + (size_t)(m0 + (tid >> 2)) * lda + k0 + (tid & 3) * 8;
        ra0 = *(const float4*)p;
        ra1 = *(const float4*)(p + 4);
    };
    auto ldgB = [&](int k0) {
        size_t off = (size_t)(k0 + (tid >> 2)) * N + n0 + (tid & 3) * 8;
        rbh = *(const uint4*)(Bhi_g + off);
        rbl = *(const uint4*)(Blo_g + off);
    };
    auto stsAB = [&](int st) {
        char* base = smem + st * STAGE;
        const int row = tid >> 2, kc = (tid & 3) * 8;
        unsigned h0, l0, h1, l1, h2, l2, h3, l3;
        split2(ra0.x, ra0.y, h0, l0);
        split2(ra0.z, ra0.w, h1, l1);
        split2(ra1.x, ra1.y, h2, l2);
        split2(ra1.z, ra1.w, h3, l3);
        *(uint2*)(base + row * APITCH + kc * 2)            = make_uint2(h0, h1);
        *(uint2*)(base + row * APITCH + kc * 2 + 8)        = make_uint2(h2, h3);
        *(uint2*)(base + A_PL + row * APITCH + kc * 2)     = make_uint2(l0, l1);
        *(uint2*)(base + A_PL + row * APITCH + kc * 2 + 8) = make_uint2(l2, l3);
        const int krow = tid >> 2, nc = (tid & 3) * 8;
        *(uint4*)(base + 2 * A_PL + krow * BPITCH + nc * 2)        = rbh;
        *(uint4*)(base + 2 * A_PL + B_PL + krow * BPITCH + nc * 2) = rbl;
    };
    auto compute = [&](int st) {
        const unsigned sOff = (unsigned)(st * STAGE);
        #pragma unroll
        for (int c = 0; c < 2; c++) {
            unsigned ah[4], al[4], bh[4], bl[4];
            ldsm4(ah, aBase + sOff + c * 32);
            ldsm4(al, aBase + sOff + A_PL + c * 32);
            ldsm4t(bh, bBase + sOff + c * (16 * BPITCH));
            ldsm4t(bl, bBase + sOff + B_PL + c * (16 * BPITCH));
            #pragma unroll
            for (int j = 0; j < 2; j++) {
                mma16816(accH[j], ah, bh + 2 * j);
                mma16816(accX[j], ah, bl + 2 * j);
                mma16816(accX[j], al, bh + 2 * j);
            }
        }
    };

    const int NIT = K / 32;
    ldgA(0); ldgB(0);
    stsAB(0);
    __syncthreads();
    int s = 0;
    for (int it = 0; it < NIT; it++) {
        if (it + 1 < NIT) { ldgA((it + 1) * 32); ldgB((it + 1) * 32); }
        compute(s);
        if (it + 1 < NIT) {
            stsAB(s ^ 1);
            __syncthreads();
            s ^= 1;
        }
    }

    // Epilogue: += Z (already in C), tanh, store in place.
    const int mBase = m0 + wm * 16 + (lane >> 2);
    #pragma unroll
    for (int j = 0; j < 2; j++) {
        const int nBase = n0 + wn * 16 + j * 8 + 2 * (lane & 3);
        #pragma unroll
        for (int h = 0; h < 2; h++) {
            const int m = mBase + h * 8;
            float d0 = accH[j][2 * h + 0] + accX[j][2 * h + 0];
            float d1 = accH[j][2 * h + 1] + accX[j][2 * h + 1];
            float* p = C + (size_t)m * ldc + nBase;
            float2 z = *(float2*)p;
            float2 o;
            o.x = tanhf(z.x + d0);
            o.y = tanhf(z.y + d1);
            *(float2*)p = o;
        }
    }
}

// ---------------------------------------------------------------------------
// Launch.
// Inputs: 0 inputs [B,T,D]  1 h0 [B,U]  2 kernel [D,U]  3 rec_kernel [U,U]
//         4 bias [U]  5 mu_c [U]  6 sigma_c [U]  7 mu_p [U]  8 sigma_p [U]
// Output: [B,T,U] float32.
// ---------------------------------------------------------------------------
extern "C" void kernel_launch(void* const* d_in, const int* in_sizes, int n_in,
                              void* d_out, int out_size) {
    const float* X    = (const float*)d_in[0];
    const float* h0   = (const float*)d_in[1];
    const float* Wk   = (const float*)d_in[2];
    const float* Wr   = (const float*)d_in[3];
    const float* bias = (const float*)d_in[4];
    const float* muc  = (const float*)d_in[5];
    const float* sic  = (const float*)d_in[6];
    const float* mup  = (const float*)d_in[7];
    const float* sip  = (const float*)d_in[8];
    float* out = (float*)d_out;

    const int U = in_sizes[4];
    const int D = in_sizes[2] / U;
    const int B = in_sizes[1] / U;
    const int T = in_sizes[0] / (B * D);

    __nv_bfloat16 *Wc_hi, *Wc_lo, *Wp_hi, *Wp_lo;
    cudaGetSymbolAddress((void**)&Wc_hi, g_Wc_hi);
    cudaGetSymbolAddress((void**)&Wc_lo, g_Wc_lo);
    cudaGetSymbolAddress((void**)&Wp_hi, g_Wp_hi);
    cudaGetSymbolAddress((void**)&Wp_lo, g_Wp_lo);

    const int SMEM_BIG  = 2 * (2 * 64 * 112 + 2 * 32 * 144);   // 47104
    const int SMEM_STEP = 2 * (2 * 32 * 112 + 2 * 32 * 80);    // 24576
    static int s_attr_done = 0;
    if (!s_attr_done) {
        cudaFuncSetAttribute(mma_gemm_big,
                             cudaFuncAttributeMaxDynamicSharedMemorySize, SMEM_BIG);
        cudaFuncSetAttribute(mma_gemm_step,
                             cudaFuncAttributeMaxDynamicSharedMemorySize, SMEM_STEP);
        s_attr_done = 1;
    }

    const float scale = sqrtf((float)D);  // reference uses sqrt(D) for BOTH masks

    // 1) Masked weights, split to bf16 hi/lo.
    build_mask_kernel<<<U, 256>>>(Wk, muc, sic, Wc_hi, Wc_lo, D, U, scale);
    build_mask_kernel<<<U, 256>>>(Wr, mup, sip, Wp_hi, Wp_lo, U, U, scale);

    // 2) Z = X @ Wc + bias -> straight into d_out.
    {
        dim3 grid(U / 64, (B * T) / 64);     // 16 x 2048
        mma_gemm_big<<<grid, 256, SMEM_BIG>>>(
            X, (size_t)D, Wc_hi, Wc_lo, bias, out, (size_t)U, U, D);
    }

    // 3) Recurrent scan: out[:,t,:] = tanh(Z_t + h_{t-1} @ Wp), one launch/step.
    {
        dim3 grid(U / 32, B / 32);           // 32 x 8 = 256 CTAs (2/SM)
        const size_t ldo = (size_t)T * U;
        for (int t = 0; t < T; t++) {
            const float* A   = (t == 0) ? h0 : (out + (size_t)(t - 1) * U);
            const size_t lda = (t == 0) ? (size_t)U : ldo;
            float* Ct = out + (size_t)t * U;   // Z term (in place)
            mma_gemm_step<<<grid, 128, SMEM_STEP>>>(
                A, lda, Wp_hi, Wp_lo, Ct, ldo, U, U);
        }
    }
}

// round 9
// speedup vs baseline: 1.4260x; 1.4260x over previous
#include <cuda_runtime.h>
#include <cuda_bf16.h>
#include <math.h>

// ---------------------------------------------------------------------------
// Static scratch (no allocation allowed).
// ---------------------------------------------------------------------------
__device__ __nv_bfloat16 g_Wc_hi[1024 * 1024];
__device__ __nv_bfloat16 g_Wc_lo[1024 * 1024];
__device__ __nv_bfloat16 g_Wp_hi[1024 * 1024];
__device__ __nv_bfloat16 g_Wp_lo[1024 * 1024];
// Double-buffered bf16 hi/lo copies of the recurrent state h [B=256][U=1024].
__device__ __nv_bfloat16 g_h_hi[2][256 * 1024];
__device__ __nv_bfloat16 g_h_lo[2][256 * 1024];

// ---------------------------------------------------------------------------
// Primitives.
// ---------------------------------------------------------------------------
__device__ __forceinline__ void ldsm4(unsigned r[4], unsigned addr) {
    asm volatile("ldmatrix.sync.aligned.m8n8.x4.shared.b16 {%0,%1,%2,%3}, [%4];"
                 : "=r"(r[0]), "=r"(r[1]), "=r"(r[2]), "=r"(r[3]) : "r"(addr));
}
__device__ __forceinline__ void ldsm4t(unsigned r[4], unsigned addr) {
    asm volatile("ldmatrix.sync.aligned.m8n8.x4.trans.shared.b16 {%0,%1,%2,%3}, [%4];"
                 : "=r"(r[0]), "=r"(r[1]), "=r"(r[2]), "=r"(r[3]) : "r"(addr));
}
__device__ __forceinline__ void mma16816(float d[4], const unsigned a[4],
                                         const unsigned b[2]) {
    asm volatile(
        "mma.sync.aligned.m16n8k16.row.col.f32.bf16.bf16.f32 "
        "{%0,%1,%2,%3}, {%4,%5,%6,%7}, {%8,%9}, {%0,%1,%2,%3};"
        : "+f"(d[0]), "+f"(d[1]), "+f"(d[2]), "+f"(d[3])
        : "r"(a[0]), "r"(a[1]), "r"(a[2]), "r"(a[3]), "r"(b[0]), "r"(b[1]));
}
__device__ __forceinline__ unsigned pack_bf(__nv_bfloat16 a, __nv_bfloat16 b) {
    unsigned short ua = *(unsigned short*)&a;
    unsigned short ub = *(unsigned short*)&b;
    return (unsigned)ua | ((unsigned)ub << 16);
}
__device__ __forceinline__ void split2(float v0, float v1,
                                       unsigned& hi, unsigned& lo) {
    __nv_bfloat16 h0 = __float2bfloat16_rn(v0);
    __nv_bfloat16 h1 = __float2bfloat16_rn(v1);
    __nv_bfloat16 l0 = __float2bfloat16_rn(v0 - __bfloat162float(h0));
    __nv_bfloat16 l1 = __float2bfloat16_rn(v1 - __bfloat162float(h1));
    hi = pack_bf(h0, h1);
    lo = pack_bf(l0, l1);
}
__device__ __forceinline__ void cpasync16(unsigned dst, const void* src) {
    asm volatile("cp.async.cg.shared.global [%0], [%1], 16;"
                 :: "r"(dst), "l"(src));
}
__device__ __forceinline__ void cp_commit() {
    asm volatile("cp.async.commit_group;");
}
__device__ __forceinline__ void cp_wait2() {
    asm volatile("cp.async.wait_group 2;");
}

// ---------------------------------------------------------------------------
// Build masked weights, split into bf16 hi/lo. One block per unit (column u).
// ---------------------------------------------------------------------------
__global__ void build_mask_kernel(const float* __restrict__ W,
                                  const float* __restrict__ mu,
                                  const float* __restrict__ sigma,
                                  __nv_bfloat16* __restrict__ Whi,
                                  __nv_bfloat16* __restrict__ Wlo,
                                  int n_in, int units, float scale) {
    int u = blockIdx.x;
    float m = mu[u];
    float s = sigma[u];
    s = fminf(fmaxf(s, 0.01f), 1.0f);
    float inv2s2 = 1.0f / (2.0f * s * s);
    float inv_nm1 = 1.0f / (float)(n_in - 1);

    float ss = 0.0f;
    for (int d = threadIdx.x; d < n_in; d += blockDim.x) {
        float diff = (float)d * inv_nm1 - m;
        float e = expf(-diff * diff * inv2s2);
        ss += e * e;
    }
    __shared__ float red[32];
    #pragma unroll
    for (int o = 16; o > 0; o >>= 1) ss += __shfl_down_sync(0xffffffffu, ss, o);
    if ((threadIdx.x & 31) == 0) red[threadIdx.x >> 5] = ss;
    __syncthreads();
    if (threadIdx.x < 32) {
        int nwarp = (blockDim.x + 31) >> 5;
        float v = (threadIdx.x < nwarp) ? red[threadIdx.x] : 0.0f;
        #pragma unroll
        for (int o = 16; o > 0; o >>= 1) v += __shfl_down_sync(0xffffffffu, v, o);
        if (threadIdx.x == 0) red[0] = v;
    }
    __syncthreads();
    float factor = scale * rsqrtf(red[0]);

    for (int d = threadIdx.x; d < n_in; d += blockDim.x) {
        float diff = (float)d * inv_nm1 - m;
        float e = expf(-diff * diff * inv2s2);
        float w = W[(size_t)d * units + u] * (e * factor);
        __nv_bfloat16 h = __float2bfloat16_rn(w);
        __nv_bfloat16 l = __float2bfloat16_rn(w - __bfloat162float(h));
        Whi[(size_t)d * units + u] = h;
        Wlo[(size_t)d * units + u] = l;
    }
}

// ---------------------------------------------------------------------------
// Convert h0 fp32 -> bf16 hi/lo planes.
// ---------------------------------------------------------------------------
__global__ void h0_split_kernel(const float* __restrict__ h0,
                                __nv_bfloat16* __restrict__ Hhi,
                                __nv_bfloat16* __restrict__ Hlo, int n) {
    int i = (blockIdx.x * blockDim.x + threadIdx.x) * 2;
    if (i < n) {
        unsigned hi, lo;
        split2(h0[i], h0[i + 1], hi, lo);
        *(unsigned*)((char*)Hhi + i * 2) = hi;
        *(unsigned*)((char*)Hlo + i * 2) = lo;
    }
}

// ---------------------------------------------------------------------------
// Big GEMM (unchanged from R6): BM=64, BN=64, BK=32, 256 threads.
// ---------------------------------------------------------------------------
__global__ void __launch_bounds__(256) mma_gemm_big(
    const float* A, size_t lda,
    const __nv_bfloat16* __restrict__ Bhi_g,
    const __nv_bfloat16* __restrict__ Blo_g,
    const float* __restrict__ bias,
    float* C, size_t ldc, int N, int K)
{
    constexpr int BM = 64;
    constexpr int APITCH = 112;
    constexpr int BPITCH = 144;
    constexpr int A_PL = BM * APITCH;
    constexpr int B_PL = 32 * BPITCH;
    constexpr int STAGE = 2 * A_PL + 2 * B_PL;

    extern __shared__ char smem[];
    const unsigned sbase = (unsigned)__cvta_generic_to_shared(smem);

    const int tid  = threadIdx.x;
    const int lane = tid & 31;
    const int wid  = tid >> 5;
    const int wm   = wid & 1;
    const int wn   = wid >> 1;
    const int m0   = blockIdx.y * BM;
    const int n0   = blockIdx.x * 64;

    float4 ra0, ra1;
    uint4  rbh, rbl;

    const unsigned aBase = sbase + (unsigned)((wm * 32 + (lane & 15)) * APITCH
                                              + (lane >> 4) * 16);
    const unsigned bBase = sbase + (unsigned)(2 * A_PL + (lane & 15) * BPITCH
                                              + (lane >> 4) * 16 + wn * 32);

    float accH[2][2][4], accX[2][2][4];
    #pragma unroll
    for (int i = 0; i < 2; i++)
        #pragma unroll
        for (int j = 0; j < 2; j++)
            #pragma unroll
            for (int q = 0; q < 4; q++) { accH[i][j][q] = 0.f; accX[i][j][q] = 0.f; }

    auto ldgA = [&](int k0) {
        const float* p = A + (size_t)(m0 + (tid >> 2)) * lda + k0 + (tid & 3) * 8;
        ra0 = *(const float4*)p;
        ra1 = *(const float4*)(p + 4);
    };
    auto ldgB = [&](int k0) {
        size_t off = (size_t)(k0 + (tid >> 3)) * N + n0 + (tid & 7) * 8;
        rbh = *(const uint4*)(Bhi_g + off);
        rbl = *(const uint4*)(Blo_g + off);
    };
    auto stsAB = [&](int st) {
        char* base = smem + st * STAGE;
        const int row = tid >> 2, kc = (tid & 3) * 8;
        unsigned h0, l0, h1, l1, h2, l2, h3, l3;
        split2(ra0.x, ra0.y, h0, l0);
        split2(ra0.z, ra0.w, h1, l1);
        split2(ra1.x, ra1.y, h2, l2);
        split2(ra1.z, ra1.w, h3, l3);
        *(uint2*)(base + row * APITCH + kc * 2)            = make_uint2(h0, h1);
        *(uint2*)(base + row * APITCH + kc * 2 + 8)        = make_uint2(h2, h3);
        *(uint2*)(base + A_PL + row * APITCH + kc * 2)     = make_uint2(l0, l1);
        *(uint2*)(base + A_PL + row * APITCH + kc * 2 + 8) = make_uint2(l2, l3);
        const int krow = tid >> 3, nc = (tid & 7) * 8;
        *(uint4*)(base + 2 * A_PL + krow * BPITCH + nc * 2)        = rbh;
        *(uint4*)(base + 2 * A_PL + B_PL + krow * BPITCH + nc * 2) = rbl;
    };
    auto compute = [&](int st) {
        const unsigned sOff = (unsigned)(st * STAGE);
        #pragma unroll
        for (int c = 0; c < 2; c++) {
            unsigned ah[2][4], al[2][4], bh[4], bl[4];
            #pragma unroll
            for (int i = 0; i < 2; i++) {
                ldsm4(ah[i], aBase + sOff + i * (16 * APITCH) + c * 32);
                ldsm4(al[i], aBase + sOff + A_PL + i * (16 * APITCH) + c * 32);
            }
            ldsm4t(bh, bBase + sOff + c * (16 * BPITCH));
            ldsm4t(bl, bBase + sOff + B_PL + c * (16 * BPITCH));
            #pragma unroll
            for (int i = 0; i < 2; i++)
                #pragma unroll
                for (int j = 0; j < 2; j++) {
                    mma16816(accH[i][j], ah[i], bh + 2 * j);
                    mma16816(accX[i][j], ah[i], bl + 2 * j);
                    mma16816(accX[i][j], al[i], bh + 2 * j);
                }
        }
    };

    const int NIT = K / 32;
    ldgA(0); ldgB(0);
    stsAB(0);
    __syncthreads();
    int s = 0;
    for (int it = 0; it < NIT; it++) {
        if (it + 1 < NIT) { ldgA((it + 1) * 32); ldgB((it + 1) * 32); }
        compute(s);
        if (it + 1 < NIT) {
            stsAB(s ^ 1);
            __syncthreads();
            s ^= 1;
        }
    }

    #pragma unroll
    for (int i = 0; i < 2; i++) {
        const int mBase = m0 + wm * 32 + i * 16 + (lane >> 2);
        #pragma unroll
        for (int j = 0; j < 2; j++) {
            const int nBase = n0 + wn * 16 + j * 8 + 2 * (lane & 3);
            #pragma unroll
            for (int h = 0; h < 2; h++) {
                const int m = mBase + h * 8;
                float d0 = accH[i][j][2 * h + 0] + accX[i][j][2 * h + 0];
                float d1 = accH[i][j][2 * h + 1] + accX[i][j][2 * h + 1];
                float2 o;
                o.x = d0 + bias[nBase];
                o.y = d1 + bias[nBase + 1];
                *(float2*)(C + (size_t)m * ldc + nBase) = o;
            }
        }
    }
}

// ---------------------------------------------------------------------------
// Step GEMM v3: fully-bf16 operands + cp.async 4-stage pipeline.
//   C = tanh(C + Ah@Bh + Ah@Bl + Al@Bh), written in place; also emits the
//   bf16 hi/lo split of the result into Hhi/Hlo (next step's A).
// BM=32, BN=64, BK=32, 256 threads (8 warps: 2m x 4n), grid 128 CTAs.
// SMEM/stage: A hi/lo 2*32*80 + B hi/lo 2*32*144 = 14336 B; 4 stages = 56 KB.
// ---------------------------------------------------------------------------
__global__ void __launch_bounds__(256) mma_gemm_step(
    const __nv_bfloat16* __restrict__ Ahi_g,
    const __nv_bfloat16* __restrict__ Alo_g,
    const __nv_bfloat16* __restrict__ Bhi_g,
    const __nv_bfloat16* __restrict__ Blo_g,
    float* C, size_t ldc,
    __nv_bfloat16* __restrict__ Hhi_o,
    __nv_bfloat16* __restrict__ Hlo_o,
    int N, int K)
{
    constexpr int APITCH = 80;                 // 32 bf16 = 64B data + pad
    constexpr int BPITCH = 144;                // 64 bf16 = 128B data + pad
    constexpr int A_PL = 32 * APITCH;
    constexpr int B_PL = 32 * BPITCH;
    constexpr int STAGE = 2 * A_PL + 2 * B_PL; // 14336

    extern __shared__ char smem[];
    const unsigned sbase = (unsigned)__cvta_generic_to_shared(smem);

    const int tid  = threadIdx.x;
    const int lane = tid & 31;
    const int wid  = tid >> 5;
    const int wm   = wid & 1;
    const int wn   = wid >> 1;
    const int m0   = blockIdx.y * 32;
    const int n0   = blockIdx.x * 64;

    // cp.async source mappings
    const int a_pl  = tid >> 7;                // 0..1 (hi/lo plane)
    const int a_row = (tid >> 2) & 31;         // m row
    const int a_ch  = tid & 3;                 // 16B chunk (8 bf16)
    const int b_row = tid >> 3;                // k row
    const int b_ch  = tid & 7;                 // 16B chunk

    const __nv_bfloat16* aSrcP = a_pl ? Alo_g : Ahi_g;
    const unsigned aDst = sbase + (unsigned)(a_pl * A_PL + a_row * APITCH + a_ch * 16);
    const unsigned bDstH = sbase + (unsigned)(2 * A_PL + b_row * BPITCH + b_ch * 16);
    const unsigned bDstL = bDstH + (unsigned)B_PL;

    auto issue_stage = [&](int st, int k0) {
        const unsigned so = (unsigned)(st * STAGE);
        cpasync16(aDst + so, aSrcP + (size_t)(m0 + a_row) * K + k0 + a_ch * 8);
        cpasync16(bDstH + so, Bhi_g + (size_t)(k0 + b_row) * N + n0 + b_ch * 8);
        cpasync16(bDstL + so, Blo_g + (size_t)(k0 + b_row) * N + n0 + b_ch * 8);
    };

    // ldmatrix bases
    const unsigned aBase = sbase + (unsigned)((wm * 16 + (lane & 15)) * APITCH
                                              + (lane >> 4) * 16);
    const unsigned bBase = sbase + (unsigned)(2 * A_PL + (lane & 15) * BPITCH
                                              + (lane >> 4) * 16 + wn * 32);

    float accH[2][4], accX[2][4];
    #pragma unroll
    for (int j = 0; j < 2; j++)
        #pragma unroll
        for (int q = 0; q < 4; q++) { accH[j][q] = 0.f; accX[j][q] = 0.f; }

    const int NIT = K / 32;
    // Prologue: stages 0..2 in flight.
    issue_stage(0, 0);   cp_commit();
    issue_stage(1, 32);  cp_commit();
    issue_stage(2, 64);  cp_commit();

    for (int it = 0; it < NIT; it++) {
        cp_wait2();
        __syncthreads();
        // Issue stage it+3 (buffer reuse is safe: it was consumed at it-1,
        // and the syncthreads above fences all consumers).
        if (it + 3 < NIT) issue_stage((it + 3) & 3, (it + 3) * 32);
        cp_commit();   // always commit (possibly empty) to keep group count

        const unsigned sOff = (unsigned)((it & 3) * STAGE);
        #pragma unroll
        for (int c = 0; c < 2; c++) {
            unsigned ah[4], al[4], bh[4], bl[4];
            ldsm4(ah, aBase + sOff + c * 32);
            ldsm4(al, aBase + sOff + A_PL + c * 32);
            ldsm4t(bh, bBase + sOff + c * (16 * BPITCH));
            ldsm4t(bl, bBase + sOff + B_PL + c * (16 * BPITCH));
            #pragma unroll
            for (int j = 0; j < 2; j++) {
                mma16816(accH[j], ah, bh + 2 * j);
                mma16816(accX[j], ah, bl + 2 * j);
                mma16816(accX[j], al, bh + 2 * j);
            }
        }
        __syncthreads();   // all warps done with stage `it` before reuse
    }

    // Epilogue: += Z (in C), tanh, store fp32 + bf16 hi/lo split of h.
    const int mBase = m0 + wm * 16 + (lane >> 2);
    #pragma unroll
    for (int j = 0; j < 2; j++) {
        const int nBase = n0 + wn * 16 + j * 8 + 2 * (lane & 3);
        #pragma unroll
        for (int h = 0; h < 2; h++) {
            const int m = mBase + h * 8;
            float d0 = accH[j][2 * h + 0] + accX[j][2 * h + 0];
            float d1 = accH[j][2 * h + 1] + accX[j][2 * h + 1];
            float* p = C + (size_t)m * ldc + nBase;
            float2 z = *(float2*)p;
            float o0 = tanhf(z.x + d0);
            float o1 = tanhf(z.y + d1);
            *(float2*)p = make_float2(o0, o1);
            unsigned hi, lo;
            split2(o0, o1, hi, lo);
            *(unsigned*)((char*)Hhi_o + ((size_t)m * N + nBase) * 2) = hi;
            *(unsigned*)((char*)Hlo_o + ((size_t)m * N + nBase) * 2) = lo;
        }
    }
}

// ---------------------------------------------------------------------------
// Launch.
// Inputs: 0 inputs [B,T,D]  1 h0 [B,U]  2 kernel [D,U]  3 rec_kernel [U,U]
//         4 bias [U]  5 mu_c [U]  6 sigma_c [U]  7 mu_p [U]  8 sigma_p [U]
// Output: [B,T,U] float32.
// ---------------------------------------------------------------------------
extern "C" void kernel_launch(void* const* d_in, const int* in_sizes, int n_in,
                              void* d_out, int out_size) {
    const float* X    = (const float*)d_in[0];
    const float* h0   = (const float*)d_in[1];
    const float* Wk   = (const float*)d_in[2];
    const float* Wr   = (const float*)d_in[3];
    const float* bias = (const float*)d_in[4];
    const float* muc  = (const float*)d_in[5];
    const float* sic  = (const float*)d_in[6];
    const float* mup  = (const float*)d_in[7];
    const float* sip  = (const float*)d_in[8];
    float* out = (float*)d_out;

    const int U = in_sizes[4];
    const int D = in_sizes[2] / U;
    const int B = in_sizes[1] / U;
    const int T = in_sizes[0] / (B * D);

    __nv_bfloat16 *Wc_hi, *Wc_lo, *Wp_hi, *Wp_lo, *Hhi, *Hlo;
    cudaGetSymbolAddress((void**)&Wc_hi, g_Wc_hi);
    cudaGetSymbolAddress((void**)&Wc_lo, g_Wc_lo);
    cudaGetSymbolAddress((void**)&Wp_hi, g_Wp_hi);
    cudaGetSymbolAddress((void**)&Wp_lo, g_Wp_lo);
    cudaGetSymbolAddress((void**)&Hhi, g_h_hi);
    cudaGetSymbolAddress((void**)&Hlo, g_h_lo);
    const size_t HPLANE = (size_t)256 * 1024;   // elements per h buffer

    const int SMEM_BIG  = 2 * (2 * 64 * 112 + 2 * 32 * 144);      // 47104
    const int SMEM_STEP = 4 * (2 * 32 * 80 + 2 * 32 * 144);       // 57344
    static int s_attr_done = 0;
    if (!s_attr_done) {
        cudaFuncSetAttribute(mma_gemm_big,
                             cudaFuncAttributeMaxDynamicSharedMemorySize, SMEM_BIG);
        cudaFuncSetAttribute(mma_gemm_step,
                             cudaFuncAttributeMaxDynamicSharedMemorySize, SMEM_STEP);
        s_attr_done = 1;
    }

    const float scale = sqrtf((float)D);  // reference uses sqrt(D) for BOTH masks

    // 1) Masked weights, split to bf16 hi/lo; h0 split into buffer 1.
    build_mask_kernel<<<U, 256>>>(Wk, muc, sic, Wc_hi, Wc_lo, D, U, scale);
    build_mask_kernel<<<U, 256>>>(Wr, mup, sip, Wp_hi, Wp_lo, U, U, scale);
    {
        int n = B * U;
        h0_split_kernel<<<(n / 2 + 255) / 256, 256>>>(
            h0, Hhi + HPLANE, Hlo + HPLANE, n);
    }

    // 2) Z = X @ Wc + bias -> straight into d_out.
    {
        dim3 grid(U / 64, (B * T) / 64);     // 16 x 2048
        mma_gemm_big<<<grid, 256, SMEM_BIG>>>(
            X, (size_t)D, Wc_hi, Wc_lo, bias, out, (size_t)U, U, D);
    }

    // 3) Recurrent scan. Step t reads h buffer (t+1)&1, writes t&1.
    {
        dim3 grid(U / 64, B / 32);           // 16 x 8 = 128 CTAs
        const size_t ldo = (size_t)T * U;
        for (int t = 0; t < T; t++) {
            const int rb = (t + 1) & 1;
            const int wb = t & 1;
            float* Ct = out + (size_t)t * U;   // Z term (in place)
            mma_gemm_step<<<grid, 256, SMEM_STEP>>>(
                Hhi + rb * HPLANE, Hlo + rb * HPLANE,
                Wp_hi, Wp_lo,
                Ct, ldo,
                Hhi + wb * HPLANE, Hlo + wb * HPLANE,
                U, U);
        }
    }
}

// round 10
// speedup vs baseline: 1.4513x; 1.0177x over previous
#include <cuda_runtime.h>
#include <cuda_bf16.h>
#include <math.h>

// ---------------------------------------------------------------------------
// Static scratch (no allocation allowed).
// ---------------------------------------------------------------------------
__device__ __nv_bfloat16 g_Wc_hi[1024 * 1024];
__device__ __nv_bfloat16 g_Wc_lo[1024 * 1024];
__device__ __nv_bfloat16 g_Wp_hi[1024 * 1024];
__device__ __nv_bfloat16 g_Wp_lo[1024 * 1024];
// Double-buffered bf16 hi/lo copies of the recurrent state h [B=256][U=1024].
__device__ __nv_bfloat16 g_h_hi[2][256 * 1024];
__device__ __nv_bfloat16 g_h_lo[2][256 * 1024];

// ---------------------------------------------------------------------------
// Primitives.
// ---------------------------------------------------------------------------
__device__ __forceinline__ void ldsm4(unsigned r[4], unsigned addr) {
    asm volatile("ldmatrix.sync.aligned.m8n8.x4.shared.b16 {%0,%1,%2,%3}, [%4];"
                 : "=r"(r[0]), "=r"(r[1]), "=r"(r[2]), "=r"(r[3]) : "r"(addr));
}
__device__ __forceinline__ void ldsm4t(unsigned r[4], unsigned addr) {
    asm volatile("ldmatrix.sync.aligned.m8n8.x4.trans.shared.b16 {%0,%1,%2,%3}, [%4];"
                 : "=r"(r[0]), "=r"(r[1]), "=r"(r[2]), "=r"(r[3]) : "r"(addr));
}
__device__ __forceinline__ void mma16816(float d[4], const unsigned a[4],
                                         const unsigned b[2]) {
    asm volatile(
        "mma.sync.aligned.m16n8k16.row.col.f32.bf16.bf16.f32 "
        "{%0,%1,%2,%3}, {%4,%5,%6,%7}, {%8,%9}, {%0,%1,%2,%3};"
        : "+f"(d[0]), "+f"(d[1]), "+f"(d[2]), "+f"(d[3])
        : "r"(a[0]), "r"(a[1]), "r"(a[2]), "r"(a[3]), "r"(b[0]), "r"(b[1]));
}
__device__ __forceinline__ unsigned pack_bf(__nv_bfloat16 a, __nv_bfloat16 b) {
    unsigned short ua = *(unsigned short*)&a;
    unsigned short ub = *(unsigned short*)&b;
    return (unsigned)ua | ((unsigned)ub << 16);
}
__device__ __forceinline__ void split2(float v0, float v1,
                                       unsigned& hi, unsigned& lo) {
    __nv_bfloat16 h0 = __float2bfloat16_rn(v0);
    __nv_bfloat16 h1 = __float2bfloat16_rn(v1);
    __nv_bfloat16 l0 = __float2bfloat16_rn(v0 - __bfloat162float(h0));
    __nv_bfloat16 l1 = __float2bfloat16_rn(v1 - __bfloat162float(h1));
    hi = pack_bf(h0, h1);
    lo = pack_bf(l0, l1);
}
__device__ __forceinline__ void cpasync16(unsigned dst, const void* src) {
    asm volatile("cp.async.cg.shared.global [%0], [%1], 16;"
                 :: "r"(dst), "l"(src));
}
__device__ __forceinline__ void cp_commit() {
    asm volatile("cp.async.commit_group;");
}
__device__ __forceinline__ void cp_wait2() {
    asm volatile("cp.async.wait_group 2;");
}

// ---------------------------------------------------------------------------
// Build masked weights, split into bf16 hi/lo. One block per unit (column u).
// ---------------------------------------------------------------------------
__global__ void build_mask_kernel(const float* __restrict__ W,
                                  const float* __restrict__ mu,
                                  const float* __restrict__ sigma,
                                  __nv_bfloat16* __restrict__ Whi,
                                  __nv_bfloat16* __restrict__ Wlo,
                                  int n_in, int units, float scale) {
    int u = blockIdx.x;
    float m = mu[u];
    float s = sigma[u];
    s = fminf(fmaxf(s, 0.01f), 1.0f);
    float inv2s2 = 1.0f / (2.0f * s * s);
    float inv_nm1 = 1.0f / (float)(n_in - 1);

    float ss = 0.0f;
    for (int d = threadIdx.x; d < n_in; d += blockDim.x) {
        float diff = (float)d * inv_nm1 - m;
        float e = expf(-diff * diff * inv2s2);
        ss += e * e;
    }
    __shared__ float red[32];
    #pragma unroll
    for (int o = 16; o > 0; o >>= 1) ss += __shfl_down_sync(0xffffffffu, ss, o);
    if ((threadIdx.x & 31) == 0) red[threadIdx.x >> 5] = ss;
    __syncthreads();
    if (threadIdx.x < 32) {
        int nwarp = (blockDim.x + 31) >> 5;
        float v = (threadIdx.x < nwarp) ? red[threadIdx.x] : 0.0f;
        #pragma unroll
        for (int o = 16; o > 0; o >>= 1) v += __shfl_down_sync(0xffffffffu, v, o);
        if (threadIdx.x == 0) red[0] = v;
    }
    __syncthreads();
    float factor = scale * rsqrtf(red[0]);

    for (int d = threadIdx.x; d < n_in; d += blockDim.x) {
        float diff = (float)d * inv_nm1 - m;
        float e = expf(-diff * diff * inv2s2);
        float w = W[(size_t)d * units + u] * (e * factor);
        __nv_bfloat16 h = __float2bfloat16_rn(w);
        __nv_bfloat16 l = __float2bfloat16_rn(w - __bfloat162float(h));
        Whi[(size_t)d * units + u] = h;
        Wlo[(size_t)d * units + u] = l;
    }
}

// ---------------------------------------------------------------------------
// Convert h0 fp32 -> bf16 hi/lo planes.
// ---------------------------------------------------------------------------
__global__ void h0_split_kernel(const float* __restrict__ h0,
                                __nv_bfloat16* __restrict__ Hhi,
                                __nv_bfloat16* __restrict__ Hlo, int n) {
    int i = (blockIdx.x * blockDim.x + threadIdx.x) * 2;
    if (i < n) {
        unsigned hi, lo;
        split2(h0[i], h0[i + 1], hi, lo);
        *(unsigned*)((char*)Hhi + i * 2) = hi;
        *(unsigned*)((char*)Hlo + i * 2) = lo;
    }
}

// ---------------------------------------------------------------------------
// Big GEMM (unchanged): BM=64, BN=64, BK=32, 256 threads.
// ---------------------------------------------------------------------------
__global__ void __launch_bounds__(256) mma_gemm_big(
    const float* A, size_t lda,
    const __nv_bfloat16* __restrict__ Bhi_g,
    const __nv_bfloat16* __restrict__ Blo_g,
    const float* __restrict__ bias,
    float* C, size_t ldc, int N, int K)
{
    constexpr int BM = 64;
    constexpr int APITCH = 112;
    constexpr int BPITCH = 144;
    constexpr int A_PL = BM * APITCH;
    constexpr int B_PL = 32 * BPITCH;
    constexpr int STAGE = 2 * A_PL + 2 * B_PL;

    extern __shared__ char smem[];
    const unsigned sbase = (unsigned)__cvta_generic_to_shared(smem);

    const int tid  = threadIdx.x;
    const int lane = tid & 31;
    const int wid  = tid >> 5;
    const int wm   = wid & 1;
    const int wn   = wid >> 1;
    const int m0   = blockIdx.y * BM;
    const int n0   = blockIdx.x * 64;

    float4 ra0, ra1;
    uint4  rbh, rbl;

    const unsigned aBase = sbase + (unsigned)((wm * 32 + (lane & 15)) * APITCH
                                              + (lane >> 4) * 16);
    const unsigned bBase = sbase + (unsigned)(2 * A_PL + (lane & 15) * BPITCH
                                              + (lane >> 4) * 16 + wn * 32);

    float accH[2][2][4], accX[2][2][4];
    #pragma unroll
    for (int i = 0; i < 2; i++)
        #pragma unroll
        for (int j = 0; j < 2; j++)
            #pragma unroll
            for (int q = 0; q < 4; q++) { accH[i][j][q] = 0.f; accX[i][j][q] = 0.f; }

    auto ldgA = [&](int k0) {
        const float* p = A + (size_t)(m0 + (tid >> 2)) * lda + k0 + (tid & 3) * 8;
        ra0 = *(const float4*)p;
        ra1 = *(const float4*)(p + 4);
    };
    auto ldgB = [&](int k0) {
        size_t off = (size_t)(k0 + (tid >> 3)) * N + n0 + (tid & 7) * 8;
        rbh = *(const uint4*)(Bhi_g + off);
        rbl = *(const uint4*)(Blo_g + off);
    };
    auto stsAB = [&](int st) {
        char* base = smem + st * STAGE;
        const int row = tid >> 2, kc = (tid & 3) * 8;
        unsigned h0, l0, h1, l1, h2, l2, h3, l3;
        split2(ra0.x, ra0.y, h0, l0);
        split2(ra0.z, ra0.w, h1, l1);
        split2(ra1.x, ra1.y, h2, l2);
        split2(ra1.z, ra1.w, h3, l3);
        *(uint2*)(base + row * APITCH + kc * 2)            = make_uint2(h0, h1);
        *(uint2*)(base + row * APITCH + kc * 2 + 8)        = make_uint2(h2, h3);
        *(uint2*)(base + A_PL + row * APITCH + kc * 2)     = make_uint2(l0, l1);
        *(uint2*)(base + A_PL + row * APITCH + kc * 2 + 8) = make_uint2(l2, l3);
        const int krow = tid >> 3, nc = (tid & 7) * 8;
        *(uint4*)(base + 2 * A_PL + krow * BPITCH + nc * 2)        = rbh;
        *(uint4*)(base + 2 * A_PL + B_PL + krow * BPITCH + nc * 2) = rbl;
    };
    auto compute = [&](int st) {
        const unsigned sOff = (unsigned)(st * STAGE);
        #pragma unroll
        for (int c = 0; c < 2; c++) {
            unsigned ah[2][4], al[2][4], bh[4], bl[4];
            #pragma unroll
            for (int i = 0; i < 2; i++) {
                ldsm4(ah[i], aBase + sOff + i * (16 * APITCH) + c * 32);
                ldsm4(al[i], aBase + sOff + A_PL + i * (16 * APITCH) + c * 32);
            }
            ldsm4t(bh, bBase + sOff + c * (16 * BPITCH));
            ldsm4t(bl, bBase + sOff + B_PL + c * (16 * BPITCH));
            #pragma unroll
            for (int i = 0; i < 2; i++)
                #pragma unroll
                for (int j = 0; j < 2; j++) {
                    mma16816(accH[i][j], ah[i], bh + 2 * j);
                    mma16816(accX[i][j], ah[i], bl + 2 * j);
                    mma16816(accX[i][j], al[i], bh + 2 * j);
                }
        }
    };

    const int NIT = K / 32;
    ldgA(0); ldgB(0);
    stsAB(0);
    __syncthreads();
    int s = 0;
    for (int it = 0; it < NIT; it++) {
        if (it + 1 < NIT) { ldgA((it + 1) * 32); ldgB((it + 1) * 32); }
        compute(s);
        if (it + 1 < NIT) {
            stsAB(s ^ 1);
            __syncthreads();
            s ^= 1;
        }
    }

    #pragma unroll
    for (int i = 0; i < 2; i++) {
        const int mBase = m0 + wm * 32 + i * 16 + (lane >> 2);
        #pragma unroll
        for (int j = 0; j < 2; j++) {
            const int nBase = n0 + wn * 16 + j * 8 + 2 * (lane & 3);
            #pragma unroll
            for (int h = 0; h < 2; h++) {
                const int m = mBase + h * 8;
                float d0 = accH[i][j][2 * h + 0] + accX[i][j][2 * h + 0];
                float d1 = accH[i][j][2 * h + 1] + accX[i][j][2 * h + 1];
                float2 o;
                o.x = d0 + bias[nBase];
                o.y = d1 + bias[nBase + 1];
                *(float2*)(C + (size_t)m * ldc + nBase) = o;
            }
        }
    }
}

// ---------------------------------------------------------------------------
// Step GEMM v4: bf16 operands, cp.async 4-stage, BK=64, ONE barrier per iter.
//   C = tanh(C + Ah@Bh + Ah@Bl + Al@Bh) in place; also writes bf16 hi/lo h.
// BM=32, BN=64, BK=64, 256 threads (8 warps: 2m x 4n), grid 128 CTAs.
// SMEM/stage: A hi/lo 2*32*144 + B hi/lo 2*64*144 = 27648 B; 4 stages = 108 KB.
// 16 K-iterations, 16 barriers per step (was 64).
// ---------------------------------------------------------------------------
__global__ void __launch_bounds__(256) mma_gemm_step(
    const __nv_bfloat16* __restrict__ Ahi_g,
    const __nv_bfloat16* __restrict__ Alo_g,
    const __nv_bfloat16* __restrict__ Bhi_g,
    const __nv_bfloat16* __restrict__ Blo_g,
    float* C, size_t ldc,
    __nv_bfloat16* __restrict__ Hhi_o,
    __nv_bfloat16* __restrict__ Hlo_o,
    int N, int K)
{
    constexpr int PITCH = 144;                  // 64 bf16 = 128B data + pad
    constexpr int A_PL = 32 * PITCH;            // 4608
    constexpr int B_PL = 64 * PITCH;            // 9216
    constexpr int STAGE = 2 * A_PL + 2 * B_PL;  // 27648

    extern __shared__ char smem[];
    const unsigned sbase = (unsigned)__cvta_generic_to_shared(smem);

    const int tid  = threadIdx.x;
    const int lane = tid & 31;
    const int wid  = tid >> 5;
    const int wm   = wid & 1;
    const int wn   = wid >> 1;
    const int m0   = blockIdx.y * 32;
    const int n0   = blockIdx.x * 64;

    // cp.async mappings.
    // A: 2 planes x 32 rows x 8 chunks(16B) = 512 slots -> 2 per thread.
    // B: 2 planes x 64 rows x 8 chunks      = 1024 slots -> 4 per thread.
    auto issue_stage = [&](int st, int k0) {
        const unsigned so = (unsigned)(st * STAGE);
        #pragma unroll
        for (int i = 0; i < 2; i++) {
            const int slot = (tid & 127) + 128 * i;
            const int row = slot >> 3, ch = slot & 7;
            const int pl = tid >> 7;
            const __nv_bfloat16* src = (pl ? Alo_g : Ahi_g)
                + (size_t)(m0 + row) * K + k0 + ch * 8;
            cpasync16(sbase + so + (unsigned)(pl * A_PL + row * PITCH + ch * 16), src);
        }
        #pragma unroll
        for (int i = 0; i < 4; i++) {
            const int slot = tid + 256 * i;
            const int pl = slot >> 9;
            const int row = (slot & 511) >> 3, ch = slot & 7;
            const __nv_bfloat16* src = (pl ? Blo_g : Bhi_g)
                + (size_t)(k0 + row) * N + n0 + ch * 8;
            cpasync16(sbase + so + (unsigned)(2 * A_PL + pl * B_PL + row * PITCH + ch * 16), src);
        }
    };

    // ldmatrix bases.
    const unsigned aBase = sbase + (unsigned)((wm * 16 + (lane & 15)) * PITCH
                                              + (lane >> 4) * 16);
    const unsigned bBase = sbase + (unsigned)(2 * A_PL + (lane & 15) * PITCH
                                              + (lane >> 4) * 16 + wn * 32);

    float accH[2][4], accX[2][4];
    #pragma unroll
    for (int j = 0; j < 2; j++)
        #pragma unroll
        for (int q = 0; q < 4; q++) { accH[j][q] = 0.f; accX[j][q] = 0.f; }

    const int NIT = K / 64;                     // 16
    issue_stage(0, 0);    cp_commit();
    issue_stage(1, 64);   cp_commit();
    issue_stage(2, 128);  cp_commit();

    for (int it = 0; it < NIT; it++) {
        cp_wait2();
        __syncthreads();       // stage `it` visible; all warps past iter it-1
        if (it + 3 < NIT) issue_stage((it + 3) & 3, (it + 3) * 64);
        cp_commit();           // keep group count aligned (may be empty)

        const unsigned sOff = (unsigned)((it & 3) * STAGE);
        #pragma unroll
        for (int c = 0; c < 4; c++) {           // four k16 chunks
            unsigned ah[4], al[4], bh[4], bl[4];
            ldsm4(ah, aBase + sOff + c * 32);
            ldsm4(al, aBase + sOff + A_PL + c * 32);
            ldsm4t(bh, bBase + sOff + c * (16 * PITCH));
            ldsm4t(bl, bBase + sOff + B_PL + c * (16 * PITCH));
            #pragma unroll
            for (int j = 0; j < 2; j++) {
                mma16816(accH[j], ah, bh + 2 * j);
                mma16816(accX[j], ah, bl + 2 * j);
                mma16816(accX[j], al, bh + 2 * j);
            }
        }
        // no trailing barrier: next iteration's barrier protects buffer reuse
    }

    // Epilogue: += Z (in C), tanh, store fp32 + bf16 hi/lo split of h.
    const int mBase = m0 + wm * 16 + (lane >> 2);
    #pragma unroll
    for (int j = 0; j < 2; j++) {
        const int nBase = n0 + wn * 16 + j * 8 + 2 * (lane & 3);
        #pragma unroll
        for (int h = 0; h < 2; h++) {
            const int m = mBase + h * 8;
            float d0 = accH[j][2 * h + 0] + accX[j][2 * h + 0];
            float d1 = accH[j][2 * h + 1] + accX[j][2 * h + 1];
            float* p = C + (size_t)m * ldc + nBase;
            float2 z = *(float2*)p;
            float o0 = tanhf(z.x + d0);
            float o1 = tanhf(z.y + d1);
            *(float2*)p = make_float2(o0, o1);
            unsigned hi, lo;
            split2(o0, o1, hi, lo);
            *(unsigned*)((char*)Hhi_o + ((size_t)m * N + nBase) * 2) = hi;
            *(unsigned*)((char*)Hlo_o + ((size_t)m * N + nBase) * 2) = lo;
        }
    }
}

// ---------------------------------------------------------------------------
// Launch.
// Inputs: 0 inputs [B,T,D]  1 h0 [B,U]  2 kernel [D,U]  3 rec_kernel [U,U]
//         4 bias [U]  5 mu_c [U]  6 sigma_c [U]  7 mu_p [U]  8 sigma_p [U]
// Output: [B,T,U] float32.
// ---------------------------------------------------------------------------
extern "C" void kernel_launch(void* const* d_in, const int* in_sizes, int n_in,
                              void* d_out, int out_size) {
    const float* X    = (const float*)d_in[0];
    const float* h0   = (const float*)d_in[1];
    const float* Wk   = (const float*)d_in[2];
    const float* Wr   = (const float*)d_in[3];
    const float* bias = (const float*)d_in[4];
    const float* muc  = (const float*)d_in[5];
    const float* sic  = (const float*)d_in[6];
    const float* mup  = (const float*)d_in[7];
    const float* sip  = (const float*)d_in[8];
    float* out = (float*)d_out;

    const int U = in_sizes[4];
    const int D = in_sizes[2] / U;
    const int B = in_sizes[1] / U;
    const int T = in_sizes[0] / (B * D);

    __nv_bfloat16 *Wc_hi, *Wc_lo, *Wp_hi, *Wp_lo, *Hhi, *Hlo;
    cudaGetSymbolAddress((void**)&Wc_hi, g_Wc_hi);
    cudaGetSymbolAddress((void**)&Wc_lo, g_Wc_lo);
    cudaGetSymbolAddress((void**)&Wp_hi, g_Wp_hi);
    cudaGetSymbolAddress((void**)&Wp_lo, g_Wp_lo);
    cudaGetSymbolAddress((void**)&Hhi, g_h_hi);
    cudaGetSymbolAddress((void**)&Hlo, g_h_lo);
    const size_t HPLANE = (size_t)256 * 1024;

    const int SMEM_BIG  = 2 * (2 * 64 * 112 + 2 * 32 * 144);      // 47104
    const int SMEM_STEP = 4 * (2 * 32 * 144 + 2 * 64 * 144);      // 110592
    static int s_attr_done = 0;
    if (!s_attr_done) {
        cudaFuncSetAttribute(mma_gemm_big,
                             cudaFuncAttributeMaxDynamicSharedMemorySize, SMEM_BIG);
        cudaFuncSetAttribute(mma_gemm_step,
                             cudaFuncAttributeMaxDynamicSharedMemorySize, SMEM_STEP);
        s_attr_done = 1;
    }

    const float scale = sqrtf((float)D);  // reference uses sqrt(D) for BOTH masks

    // 1) Masked weights, split to bf16 hi/lo; h0 split into buffer 1.
    build_mask_kernel<<<U, 256>>>(Wk, muc, sic, Wc_hi, Wc_lo, D, U, scale);
    build_mask_kernel<<<U, 256>>>(Wr, mup, sip, Wp_hi, Wp_lo, U, U, scale);
    {
        int n = B * U;
        h0_split_kernel<<<(n / 2 + 255) / 256, 256>>>(
            h0, Hhi + HPLANE, Hlo + HPLANE, n);
    }

    // 2) Z = X @ Wc + bias -> straight into d_out.
    {
        dim3 grid(U / 64, (B * T) / 64);     // 16 x 2048
        mma_gemm_big<<<grid, 256, SMEM_BIG>>>(
            X, (size_t)D, Wc_hi, Wc_lo, bias, out, (size_t)U, U, D);
    }

    // 3) Recurrent scan. Step t reads h buffer (t+1)&1, writes t&1.
    {
        dim3 grid(U / 64, B / 32);           // 16 x 8 = 128 CTAs
        const size_t ldo = (size_t)T * U;
        for (int t = 0; t < T; t++) {
            const int rb = (t + 1) & 1;
            const int wb = t & 1;
            float* Ct = out + (size_t)t * U;   // Z term (in place)
            mma_gemm_step<<<grid, 256, SMEM_STEP>>>(
                Hhi + rb * HPLANE, Hlo + rb * HPLANE,
                Wp_hi, Wp_lo,
                Ct, ldo,
                Hhi + wb * HPLANE, Hlo + wb * HPLANE,
                U, U);
        }
    }
}